// round 10
// baseline (speedup 1.0000x reference)
#include <cuda_runtime.h>
#include <cuda_bf16.h>
#include <cstdint>

#define HH 150
#define APITCH 152          // g_A/g_B row pitch (floats)

#define EPITCH 392          // E row pitch in u32 words
#define H1PITCH 88          // h1 row pitch in u32 words
#define WABPITCH 36         // k1 weight row pitch (u32 words)

// Quartered packed-fragment W blob: per k16-step: [nq:4][lane:32][12 words]
#define PKS 1536            // words per k-step
#define SLAB_W (2 * PKS)    // 2 ks per fetch slab = 3072 words = 12288 B
#define W1C_WORDS (48 * PKS)
#define W2_WORDS  (10 * PKS)

// ---------------- device scratch ----------------
__device__ __align__(16) uint32_t      g_Ebf[1536 * EPITCH];
__device__ __align__(16) __nv_bfloat16 g_wabT[12 * 320 * 72];
__device__ __align__(16) uint32_t      g_w1cP[W1C_WORDS];
__device__ __align__(16) uint32_t      g_w2P[W2_WORDS];
__device__ __align__(16) float g_A[1536 * APITCH];
__device__ __align__(16) float g_B[1536 * APITCH];
__device__ float g_SP[4][8 * 192 * 192];   // per-nq partial scores

// ---------------- helpers ----------------
__device__ __forceinline__ uint32_t smem_u32(const void* p) {
    uint32_t a;
    asm("{ .reg .u64 t; cvta.to.shared.u64 t, %1; cvt.u32.u64 %0, t; }" : "=r"(a) : "l"(p));
    return a;
}
__device__ __forceinline__ uint32_t packbf(float lo, float hi) {
    uint32_t d; asm("cvt.rn.bf16x2.f32 %0, %1, %2;" : "=r"(d) : "f"(hi), "f"(lo)); return d;
}
__device__ __forceinline__ uint32_t bmul2(uint32_t a, uint32_t b) {
    uint32_t d; asm("mul.rn.bf16x2 %0, %1, %2;" : "=r"(d) : "r"(a), "r"(b)); return d;
}
__device__ __forceinline__ void mma16816(float* d, const uint32_t* a, const uint32_t* b,
                                         const float* c) {
    asm volatile(
        "mma.sync.aligned.m16n8k16.row.col.f32.bf16.bf16.f32 "
        "{%0,%1,%2,%3}, {%4,%5,%6,%7}, {%8,%9}, {%10,%11,%12,%13};"
        : "=f"(d[0]), "=f"(d[1]), "=f"(d[2]), "=f"(d[3])
        : "r"(a[0]), "r"(a[1]), "r"(a[2]), "r"(a[3]), "r"(b[0]), "r"(b[1]),
          "f"(c[0]), "f"(c[1]), "f"(c[2]), "f"(c[3]));
}
#define MBAR_INIT(mb, cnt) asm volatile("mbarrier.init.shared.b64 [%0], %1;" :: "r"((uint32_t)(mb)), "r"((uint32_t)(cnt)) : "memory")
#define MBAR_EXPECT_TX(mb, n) asm volatile("mbarrier.arrive.expect_tx.shared.b64 _, [%0], %1;" :: "r"((uint32_t)(mb)), "r"((uint32_t)(n)) : "memory")
#define MBAR_ARRIVE(mb) asm volatile("mbarrier.arrive.release.cta.shared::cta.b64 _, [%0];" :: "r"((uint32_t)(mb)) : "memory")
#define FENCE_ASYNC() asm volatile("fence.proxy.async.shared::cta;" ::: "memory")
#define NBAR(id, cnt) asm volatile("bar.sync %0, %1;" :: "r"(id), "r"(cnt) : "memory")
#define MBAR_WAIT(mb, ph) do { \
    uint32_t _m = (uint32_t)(mb); uint32_t _p = (uint32_t)(ph); uint32_t _d; \
    asm volatile("{\n\t.reg .pred p;\n\tmbarrier.try_wait.parity.acquire.cta.shared::cta.b64 p, [%1], %2;\n\tselp.b32 %0, 1, 0, p;\n\t}" \
        : "=r"(_d) : "r"(_m), "r"(_p) : "memory"); \
    if (!_d) { \
        asm volatile("{\n\t.reg .pred P1;\n\tWL_%=:\n\tmbarrier.try_wait.parity.acquire.cta.shared::cta.b64 P1, [%0], %1, 0x989680;\n\t@P1 bra.uni WD_%=;\n\tbra.uni WL_%=;\n\tWD_%=:\n\t}" \
            :: "r"(_m), "r"(_p) : "memory"); \
    } } while (0)
__device__ __forceinline__ void bulk_g2s(uint32_t dst, const void* src, uint32_t bytes, uint32_t mbar) {
    asm volatile("cp.async.bulk.shared::cta.global.mbarrier::complete_tx::bytes [%0], [%1], %2, [%3];"
        :: "r"(dst), "l"(src), "r"(bytes), "r"(mbar) : "memory");
}

// ---------------- prep: E -> interleaved bf16x2 ----------------
__global__ void kprep_e(const float* __restrict__ E) {
    int idx = blockIdx.x * 256 + threadIdx.x;
    if (idx >= 1536 * EPITCH) return;
    int r = idx / EPITCH, pos = idx % EPITCH;
    int g = pos >> 3, wi = pos & 7, q = wi >> 1, h = wi & 1;
    int kw = g * 8 + q + 4 * h;
    uint32_t v = 0;
    if (kw < 384) {
        float2 e = *reinterpret_cast<const float2*>(E + (size_t)r * 768 + 2 * kw);
        v = packbf(e.x, e.y);
    }
    g_Ebf[idx] = v;
}

// ---------------- prep: weights ----------------
#define WAB_N (12 * 320 * 72)
__global__ void kprep_w(const float* __restrict__ W1, const float* __restrict__ W2) {
    int idx = blockIdx.x * 256 + threadIdx.x;
    if (idx < WAB_N) {
        int c = idx / (320 * 72), rem = idx % (320 * 72);
        int n = rem / 72, kk = rem % 72;
        float v = 0.f;
        if (kk < 64) {
            int kg = c * 64 + kk;
            if (n < 160) { if (n < HH) v = W1[(size_t)kg * HH + n]; }
            else { int h = n - 160; if (h < HH) v = W1[(size_t)(768 + kg) * HH + h]; }
        }
        g_wabT[idx] = __float2bfloat16(v);
    } else if (idx < WAB_N + W1C_WORDS + W2_WORDS) {
        int t = idx - WAB_N;
        bool isW2 = (t >= W1C_WORDS);
        int r = isW2 ? (t - W1C_WORDS) : t;
        int ks = r / PKS, r1 = r % PKS;
        int nqq = r1 / 384, r2 = r1 % 384;
        int lane = r2 / 12, ws = r2 % 12;
        uint32_t v = 0;
        if (ws < 10) {
            int l = ws >> 1, e = ws & 1;
            int gq = lane >> 2, qq = lane & 3;
            int nb = nqq * 5 + l;
            int kwl = ks * 8 + qq + e * 4;
            int n = nb * 8 + gq;
            float v0 = 0.f, v1 = 0.f;
            if (n < HH) {
                if (isW2) {
                    int k0 = 2 * kwl;
                    if (k0 < HH)     v0 = W2[(size_t)k0 * HH + n];
                    if (k0 + 1 < HH) v1 = W2[(size_t)(k0 + 1) * HH + n];
                } else {
                    int k0 = 2 * kwl;   // ks spans 0..47 -> k0 < 768
                    v0 = W1[(size_t)(1536 + k0) * HH + n];
                    v1 = W1[(size_t)(1536 + k0 + 1) * HH + n];
                }
            }
            v = packbf(v0, v1);
        }
        if (isW2) g_w2P[r] = v; else g_w1cP[r] = v;
    }
}

// ---------------- k1: seeds GEMM -> g_A,g_B (pitch 152) ----------------
#define K1_E_BYTES (32 * EPITCH * 4)
#define K1_W_BYTES (320 * WABPITCH * 4)
#define K1_BAR_OFF (K1_E_BYTES + 2 * K1_W_BYTES)
#define K1_SMEM    (K1_BAR_OFF + 64)

__global__ __launch_bounds__(256, 1)
void k1_mma(const float* __restrict__ b1) {
    extern __shared__ __align__(128) char smem[];
    uint32_t* sE = (uint32_t*)smem;
    uint32_t* sW[2] = { (uint32_t*)(smem + K1_E_BYTES),
                        (uint32_t*)(smem + K1_E_BYTES + K1_W_BYTES) };
    const uint32_t barE = smem_u32(smem + K1_BAR_OFF);
    const uint32_t barW[2] = { barE + 8, barE + 16 };
    const int tid = threadIdx.x, w = tid >> 5, lane = tid & 31;
    const int gq = lane >> 2, qq = lane & 3;
    const int r0 = blockIdx.x * 32;

    if (tid == 0) {
        MBAR_INIT(barE, 1); MBAR_INIT(barW[0], 1); MBAR_INIT(barW[1], 1);
        FENCE_ASYNC();
        MBAR_EXPECT_TX(barE, K1_E_BYTES);
        bulk_g2s(smem_u32(sE), g_Ebf + (size_t)r0 * EPITCH, K1_E_BYTES, barE);
        MBAR_EXPECT_TX(barW[0], K1_W_BYTES);
        bulk_g2s(smem_u32(sW[0]), g_wabT, K1_W_BYTES, barW[0]);
        MBAR_EXPECT_TX(barW[1], K1_W_BYTES);
        bulk_g2s(smem_u32(sW[1]), g_wabT + (size_t)320 * 72, K1_W_BYTES, barW[1]);
    }
    __syncthreads();
    MBAR_WAIT(barE, 0);

    float acc[2][5][4];
#pragma unroll
    for (int t = 0; t < 2; t++)
#pragma unroll
        for (int l = 0; l < 5; l++)
#pragma unroll
            for (int u = 0; u < 4; u++) acc[t][l][u] = 0.f;

    const uint32_t* e0p = sE + (size_t)gq * EPITCH;
    const uint32_t* e1p = e0p + 8 * EPITCH;
    const uint32_t* e2p = e0p + 16 * EPITCH;
    const uint32_t* e3p = e0p + 24 * EPITCH;

    for (int c = 0; c < 12; c++) {
        MBAR_WAIT(barW[c & 1], (c >> 1) & 1);
        const uint32_t* Wb = sW[c & 1];
#pragma unroll
        for (int ks = 0; ks < 4; ks++) {
            int kb = c * 32 + ks * 8 + 2 * qq;
            uint2 e0 = *(const uint2*)(e0p + kb);
            uint2 e1 = *(const uint2*)(e1p + kb);
            uint2 e2 = *(const uint2*)(e2p + kb);
            uint2 e3 = *(const uint2*)(e3p + kb);
            uint32_t a0[4] = { e0.x, e1.x, e0.y, e1.y };
            uint32_t a1[4] = { e2.x, e3.x, e2.y, e3.y };
#pragma unroll
            for (int l = 0; l < 5; l++) {
                int nrow = (w * 5 + l) * 8 + gq;
                uint32_t b[2] = { Wb[nrow * WABPITCH + ks * 8 + qq],
                                  Wb[nrow * WABPITCH + ks * 8 + qq + 4] };
                mma16816(acc[0][l], a0, b, acc[0][l]);
                mma16816(acc[1][l], a1, b, acc[1][l]);
            }
        }
        __syncthreads();
        if (tid == 0 && c + 2 < 12) {
            MBAR_EXPECT_TX(barW[c & 1], K1_W_BYTES);
            bulk_g2s(smem_u32(sW[c & 1]), g_wabT + (size_t)(c + 2) * 320 * 72,
                     K1_W_BYTES, barW[c & 1]);
        }
    }

#pragma unroll
    for (int t = 0; t < 2; t++)
#pragma unroll
        for (int l = 0; l < 5; l++) {
            int n0 = (w * 5 + l) * 8 + 2 * qq;
            int ra = r0 + 16 * t + gq, rb = ra + 8;
#pragma unroll
            for (int u = 0; u < 4; u++) {
                int row = (u < 2) ? ra : rb;
                int n = n0 + (u & 1);
                float v = acc[t][l][u];
                if (n < 160) { if (n < HH) g_A[(size_t)row * APITCH + n] = v + __ldg(b1 + n); }
                else { int h = n - 160; if (h < HH) g_B[(size_t)row * APITCH + h] = v; }
            }
        }
}

// ---------------- k2: fused pair MLP — 512 thr, 16 warps (4/SMSP) ----------------
// Compact grid (156, 8). Warp w: mh=w>>2 (0..3, m32), nq=w&3 (n40 quarter).
// Tile: TI=16 x TJ=8 = 128 pairs.
#define K2_EI_OFF   0                                  // 16*392*4 = 25088
#define K2_EJ_OFF   25088                              // 8*392*4  = 12544
#define K2_W_OFF    37632                              // 4 x 12288 = 49152
#define K2_H1_OFF   86784                              // 128*88*4 = 45056
#define K2_BW_OFF   131840                             // b2|W3: 1216
#define K2_BAR_OFF  133056
#define K2_SMEM     (K2_BAR_OFF + 128)                 // 133184

__global__ __launch_bounds__(512, 1)
void k2_mma(const float* __restrict__ b2,
            const float* __restrict__ W3) {
    const int bz = blockIdx.y;
    const int x = blockIdx.x;
    const int cumt[12] = {0, 2, 6, 12, 20, 30, 42, 56, 72, 90, 110, 132};
    int ti = 0;
#pragma unroll
    for (int t = 1; t < 12; t++)
        if (cumt[t] <= x) ti = t;
    const int tj = x - cumt[ti];

    extern __shared__ __align__(128) char smem[];
    uint32_t* sEi = (uint32_t*)(smem + K2_EI_OFF);
    uint32_t* sEj = (uint32_t*)(smem + K2_EJ_OFF);
    uint32_t* sWr = (uint32_t*)(smem + K2_W_OFF);      // ring: 4 x SLAB_W
    uint32_t* sH1 = (uint32_t*)(smem + K2_H1_OFF);
    float*    sB2 = (float*)(smem + K2_BW_OFF);
    float*    sW3 = sB2 + 152;
    const uint32_t barE = smem_u32(smem + K2_BAR_OFF);
    const uint32_t barW0 = barE + 8;    // barW[b] = barW0 + 8b
    const uint32_t barC0 = barE + 40;   // barC[b] = barC0 + 8b
    const int tid = threadIdx.x, w = tid >> 5, lane = tid & 31;
    const int mh = w >> 2, nq = w & 3;
    const int gq = lane >> 2, qq = lane & 3;

    if (tid == 0) {
        MBAR_INIT(barE, 1);
#pragma unroll
        for (int b = 0; b < 4; b++) { MBAR_INIT(barW0 + 8 * b, 1); MBAR_INIT(barC0 + 8 * b, 16); }
        FENCE_ASYNC();
        MBAR_EXPECT_TX(barE, (16 + 8) * EPITCH * 4);
        bulk_g2s(smem_u32(sEi), g_Ebf + ((size_t)bz * 192 + ti * 16) * EPITCH, 16 * EPITCH * 4, barE);
        bulk_g2s(smem_u32(sEj), g_Ebf + ((size_t)bz * 192 + tj * 8) * EPITCH, 8 * EPITCH * 4, barE);
#pragma unroll
        for (int f = 0; f < 4; f++) {
            MBAR_EXPECT_TX(barW0 + 8 * f, SLAB_W * 4);
            bulk_g2s(smem_u32(sWr + f * SLAB_W), g_w1cP + (size_t)f * SLAB_W, SLAB_W * 4, barW0 + 8 * f);
        }
    }
    // stage b2/W3; zero sH1 pad words kw 76..79
    if (tid < 152) sB2[tid] = (tid < HH) ? b2[tid] : 0.f;
    else if (tid < 304) { int h = tid - 152; sW3[h] = (h < HH) ? W3[h] : 0.f; }
    if (tid < 128 * 4)
        sH1[(tid >> 2) * H1PITCH + 76 + (tid & 3)] = 0;
    __syncthreads();
    MBAR_WAIT(barE, 0);

    float acc[2][5][4];
#pragma unroll
    for (int t = 0; t < 2; t++)
#pragma unroll
        for (int l = 0; l < 5; l++)
#pragma unroll
            for (int u = 0; u < 4; u++) acc[t][l][u] = 0.f;

    const uint32_t* eI0 = sEi + (size_t)(4 * mh + 0) * EPITCH;
    const uint32_t* eI1 = sEi + (size_t)(4 * mh + 1) * EPITCH;
    const uint32_t* eI2 = sEi + (size_t)(4 * mh + 2) * EPITCH;
    const uint32_t* eI3 = sEi + (size_t)(4 * mh + 3) * EPITCH;
    const uint32_t* eJp = sEj + (size_t)gq * EPITCH;
    const int bw_off = nq * 384 + lane * 12;
    const bool full_n = (nq != 3);   // nq==3 skips all-zero n-block 19

    // 5 n-blocks per quarter: 2x uint4 (blocks 0-3) + uint2 (block 4)
#define MMA_NBLOCKS(ACC, a0, a1, bp) do { \
        _Pragma("unroll") \
        for (int m = 0; m < 2; m++) { \
            uint4 bb = *(const uint4*)((bp) + m * 4); \
            uint32_t b0[2] = { bb.x, bb.y }; \
            uint32_t b1r[2] = { bb.z, bb.w }; \
            mma16816(ACC[0][2 * m],     a0, b0,  ACC[0][2 * m]); \
            mma16816(ACC[1][2 * m],     a1, b0,  ACC[1][2 * m]); \
            mma16816(ACC[0][2 * m + 1], a0, b1r, ACC[0][2 * m + 1]); \
            mma16816(ACC[1][2 * m + 1], a1, b1r, ACC[1][2 * m + 1]); \
        } \
        if (full_n) { \
            uint2 b4 = *(const uint2*)((bp) + 8); \
            uint32_t b0[2] = { b4.x, b4.y }; \
            mma16816(ACC[0][4], a0, b0, ACC[0][4]); \
            mma16816(ACC[1][4], a1, b0, ACC[1][4]); \
        } \
    } while (0)

    // ---- layer 1: 24 slabs of 2 k16-steps through the 4-buffer ring ----
    for (int f = 0; f < 24; f++) {
        const int buf = f & 3;
        const uint32_t bw = barW0 + 8 * buf, bc = barC0 + 8 * buf;
        MBAR_WAIT(bw, (f >> 2) & 1);
        const uint32_t* Wb = sWr + buf * SLAB_W;
#pragma unroll
        for (int ks = 0; ks < 2; ks++) {
            int kb = f * 16 + ks * 8 + 2 * qq;
            uint2 ej = *(const uint2*)(eJp + kb);
            uint2 e0 = *(const uint2*)(eI0 + kb);
            uint2 e1 = *(const uint2*)(eI1 + kb);
            uint2 e2 = *(const uint2*)(eI2 + kb);
            uint2 e3 = *(const uint2*)(eI3 + kb);
            uint32_t a0[4] = { bmul2(e0.x, ej.x), bmul2(e1.x, ej.x),
                               bmul2(e0.y, ej.y), bmul2(e1.y, ej.y) };
            uint32_t a1[4] = { bmul2(e2.x, ej.x), bmul2(e3.x, ej.x),
                               bmul2(e2.y, ej.y), bmul2(e3.y, ej.y) };
            const uint32_t* bp = Wb + ks * PKS + bw_off;
            MMA_NBLOCKS(acc, a0, a1, bp);
        }
        __syncwarp();
        if (lane == 0) MBAR_ARRIVE(bc);
        if (w == 0 && lane == 0) {
            MBAR_WAIT(bc, (f >> 2) & 1);
            int nf = f + 4;
            const uint32_t* src = (nf < 24) ? g_w1cP + (size_t)nf * SLAB_W
                                            : g_w2P + (size_t)(nf - 24) * SLAB_W;
            MBAR_EXPECT_TX(bw, SLAB_W * 4);
            bulk_g2s(smem_u32(sWr + buf * SLAB_W), src, SLAB_W * 4, bw);
        }
    }

    // ---- epilogue 1: + seeds (L2 gmem), ReLU, bf16 -> sH1 ----
    const float* Bj = g_B + ((size_t)bz * 192 + tj * 8 + gq) * APITCH;
#pragma unroll
    for (int t = 0; t < 2; t++) {
        const float* A0 = g_A + ((size_t)bz * 192 + ti * 16 + 4 * mh + 2 * t) * APITCH;
        const float* A1 = A0 + APITCH;
#pragma unroll
        for (int l = 0; l < 5; l++) {
            if (l == 4 && !full_n) break;    // dead n-block; pad pre-zeroed
            int nbg = nq * 5 + l;
            int h0 = nbg * 8 + 2 * qq;
            float v0 = 0.f, v1 = 0.f, v2 = 0.f, v3 = 0.f;
            if (h0 < HH) {
                float2 a0v = *(const float2*)(A0 + h0);
                float2 a1v = *(const float2*)(A1 + h0);
                float2 bjv = *(const float2*)(Bj + h0);
                v0 = fmaxf(acc[t][l][0] + a0v.x + bjv.x, 0.f);
                v1 = fmaxf(acc[t][l][1] + a0v.y + bjv.y, 0.f);
                v2 = fmaxf(acc[t][l][2] + a1v.x + bjv.x, 0.f);
                v3 = fmaxf(acc[t][l][3] + a1v.y + bjv.y, 0.f);
            }
            int kw = nbg * 4 + qq;
            int ilvw = ((kw >> 3) << 3) + 2 * (kw & 3) + ((kw >> 2) & 1);
            sH1[(32 * mh + 16 * t + gq) * H1PITCH + ilvw]     = packbf(v0, v1);
            sH1[(32 * mh + 16 * t + 8 + gq) * H1PITCH + ilvw] = packbf(v2, v3);
        }
    }
    NBAR(1 + mh, 128);         // the 4 nq warps of this mh exchange h1 slices

    // ---- layer 2: K=160 = fetch slots f=24..28 (2 ks each) ----
    float ac2[2][5][4];
#pragma unroll
    for (int t = 0; t < 2; t++)
#pragma unroll
        for (int l = 0; l < 5; l++)
#pragma unroll
            for (int u = 0; u < 4; u++) ac2[t][l][u] = 0.f;

    const uint32_t* h0p = sH1 + (size_t)(32 * mh + gq) * H1PITCH;
    const uint32_t* h1p = h0p + 8 * H1PITCH;
    const uint32_t* h2p = h0p + 16 * H1PITCH;
    const uint32_t* h3p = h0p + 24 * H1PITCH;

#pragma unroll
    for (int f = 24; f < 29; f++) {
        const int buf = f & 3;
        const uint32_t bw = barW0 + 8 * buf, bc = barC0 + 8 * buf;
        MBAR_WAIT(bw, (f >> 2) & 1);
        const uint32_t* Wb = sWr + buf * SLAB_W;
#pragma unroll
        for (int ks2 = 0; ks2 < 2; ks2++) {
            int kb = (f - 24) * 16 + ks2 * 8 + 2 * qq;
            uint2 x0 = *(const uint2*)(h0p + kb);
            uint2 x1 = *(const uint2*)(h1p + kb);
            uint2 x2 = *(const uint2*)(h2p + kb);
            uint2 x3 = *(const uint2*)(h3p + kb);
            uint32_t a0[4] = { x0.x, x1.x, x0.y, x1.y };
            uint32_t a1[4] = { x2.x, x3.x, x2.y, x3.y };
            const uint32_t* bp = Wb + ks2 * PKS + bw_off;
            MMA_NBLOCKS(ac2, a0, a1, bp);
        }
        if (f == 24) {   // refill f=28 (W2 ks 8-9) into buf0
            __syncwarp();
            if (lane == 0) MBAR_ARRIVE(bc);
            if (w == 0 && lane == 0) {
                MBAR_WAIT(bc, (f >> 2) & 1);
                MBAR_EXPECT_TX(bw, SLAB_W * 4);
                bulk_g2s(smem_u32(sWr + buf * SLAB_W), g_w2P + (size_t)4 * SLAB_W,
                         SLAB_W * 4, bw);
            }
        }
    }

    // ---- epilogue 2: +b2, ReLU, dot W3; per-nq partial to g_SP[nq] ----
    float sp[2][2] = { {0.f, 0.f}, {0.f, 0.f} };
#pragma unroll
    for (int t = 0; t < 2; t++)
#pragma unroll
        for (int l = 0; l < 5; l++) {
            if (l == 4 && !full_n) break;
            int h0 = (nq * 5 + l) * 8 + 2 * qq;
            if (h0 < HH) {
                float2 bv = *(const float2*)(sB2 + h0);
                float2 wv = *(const float2*)(sW3 + h0);
                sp[t][0] += fmaxf(ac2[t][l][0] + bv.x, 0.f) * wv.x
                          + fmaxf(ac2[t][l][1] + bv.y, 0.f) * wv.y;
                sp[t][1] += fmaxf(ac2[t][l][2] + bv.x, 0.f) * wv.x
                          + fmaxf(ac2[t][l][3] + bv.y, 0.f) * wv.y;
            }
        }
#pragma unroll
    for (int t = 0; t < 2; t++)
#pragma unroll
        for (int s = 0; s < 2; s++) {
            sp[t][s] += __shfl_xor_sync(0xffffffffu, sp[t][s], 1);
            sp[t][s] += __shfl_xor_sync(0xffffffffu, sp[t][s], 2);
        }
    if (qq == 0) {
        float* dst = g_SP[nq];
#pragma unroll
        for (int t = 0; t < 2; t++)
#pragma unroll
            for (int s = 0; s < 2; s++) {
                int r = 32 * mh + 16 * t + 8 * s + gq;
                int ip = ti * 16 + (r >> 3), jp = tj * 8 + (r & 7);
                if (jp < ip)
                    dst[((size_t)bz * 192 + ip) * 192 + jp] = sp[t][s];
            }
    }
}

// ---------------- k3: tril softmax (sums the 4 partial-score arrays) ----------------
__global__ void k3_softmax(float* __restrict__ out, const float* __restrict__ b3) {
    const int i = blockIdx.x, b = blockIdx.y, j = threadIdx.x;
    const float b3v = __ldg(b3);
    float val;
    if (j < i) {
        size_t idx = ((size_t)b * 192 + i) * 192 + j;
        val = (g_SP[0][idx] + g_SP[1][idx]) + (g_SP[2][idx] + g_SP[3][idx]) + b3v;
    } else if (j == i) val = 0.f;
    else               val = -1e30f;

    __shared__ float red[6];
    float m = val;
#pragma unroll
    for (int o = 16; o; o >>= 1) m = fmaxf(m, __shfl_xor_sync(0xffffffffu, m, o));
    if ((j & 31) == 0) red[j >> 5] = m;
    __syncthreads();
    float M = fmaxf(fmaxf(fmaxf(red[0], red[1]), fmaxf(red[2], red[3])), fmaxf(red[4], red[5]));
    __syncthreads();
    float e = (j <= i) ? expf(val - M) : 0.f;
    float s = e;
#pragma unroll
    for (int o = 16; o; o >>= 1) s += __shfl_xor_sync(0xffffffffu, s, o);
    if ((j & 31) == 0) red[j >> 5] = s;
    __syncthreads();
    float S = red[0] + red[1] + red[2] + red[3] + red[4] + red[5];
    out[((size_t)b * 192 + i) * 192 + j] = (j <= i) ? (e / S) : -1000.0f;
}

// ---------------------------------------------------------------------------
extern "C" void kernel_launch(void* const* d_in, const int* in_sizes, int n_in,
                              void* d_out, int out_size) {
    const float* E  = (const float*)d_in[0];
    const float* W1 = (const float*)d_in[1];
    const float* b1 = (const float*)d_in[2];
    const float* W2 = (const float*)d_in[3];
    const float* b2 = (const float*)d_in[4];
    const float* W3 = (const float*)d_in[5];
    const float* b3 = (const float*)d_in[6];
    float* out = (float*)d_out;

    cudaFuncSetAttribute(k1_mma, cudaFuncAttributeMaxDynamicSharedMemorySize, K1_SMEM);
    cudaFuncSetAttribute(k2_mma, cudaFuncAttributeMaxDynamicSharedMemorySize, K2_SMEM);

    kprep_e<<<(1536 * EPITCH + 255) / 256, 256>>>(E);
    kprep_w<<<(WAB_N + W1C_WORDS + W2_WORDS + 255) / 256, 256>>>(W1, W2);
    k1_mma<<<48, 256, K1_SMEM>>>(b1);
    k2_mma<<<dim3(156, 8), 512, K2_SMEM>>>(b2, W3);
    k3_softmax<<<dim3(192, 8), 192>>>(out, b3);
}